// round 15
// baseline (speedup 1.0000x reference)
#include <cuda_runtime.h>
#include <cuda_bf16.h>
#include <cstdint>

// Problem constants
#define B_DIM   2048
#define P_DIM   50
#define K_DIM   28672            // 512*7*8
#define NP      56               // P padded to 56 (7 n8-tiles)
#define KS      28               // K splits (uniform NITER=32, grid 448)
#define KCHUNK  (K_DIM / KS)     // 1024
#define KB      32               // K floats per pipeline stage
#define NITER   (KCHUNK / KB)    // 32
#define MT      128              // M tile
#define MTILES  (B_DIM / MT)     // 16
#define STAGES  3
#define BPITCH  40               // bf16 pitch (80B rows; LDS.32 frag reads conflict-free)

// Staged tiles: fp32, exact 128B rows, XOR granule swizzle
#define AS_BYTES (MT * KB * 4)               // 16384
#define BS_BYTES (NP * KB * 4)               // 7168
#define STAGE_BYTES (AS_BYTES + BS_BYTES)    // 23552
#define BF_BYTES (NP * BPITCH * 2)           // 4480 single shared bf16 B tile
#define SMEM_BYTES (STAGES * STAGE_BYTES + BF_BYTES)   // 75136 (3 CTAs/SM: 220KB < 228KB)

// ---------------------------------------------------------------------------
__device__ __forceinline__ void cpa16(uint32_t saddr, const void* gaddr) {
    asm volatile("cp.async.cg.shared.global [%0], [%1], 16;\n"
                 :: "r"(saddr), "l"(gaddr));
}
// zero-fill variant: src-size=0 reads nothing, fills 16B of zeros
__device__ __forceinline__ void cpa16z(uint32_t saddr, const void* gaddr, int srcsz) {
    asm volatile("cp.async.cg.shared.global [%0], [%1], 16, %2;\n"
                 :: "r"(saddr), "l"(gaddr), "r"(srcsz));
}
__device__ __forceinline__ void cpa_commit() {
    asm volatile("cp.async.commit_group;\n" ::: "memory");
}
__device__ __forceinline__ void cpa_wait2() {
    asm volatile("cp.async.wait_group 2;\n" ::: "memory");
}
__device__ __forceinline__ uint32_t pack_bf16x2(float2 v) {
    __nv_bfloat162 h = __floats2bfloat162_rn(v.x, v.y);
    return *(uint32_t*)&h;
}
// vector reduction: out[0] += v0, out[1] += v1 in ONE LTS op (sm_90+)
__device__ __forceinline__ void red_v2(float* gaddr, float v0, float v1) {
    asm volatile("red.global.add.v2.f32 [%0], {%1, %2};\n"
                 :: "l"(gaddr), "f"(v0), "f"(v1) : "memory");
}

// ---------------------------------------------------------------------------
// Fused GEMM + distance accumulation, single kernel.
// Per iteration: cp.async fp32 A+B (3 stages) -> convert B fp32->bf16 into a
// single shared tile (warps 0-6; exact p2 accumulated from fp32 registers)
// -> MMA with fp32 A fragments (x^2 fused) and bf16 B fragments (LDS.32).
// Block epilogue: v2-RED  x2_b + p2_p - 2*xp  into out[b,p] (relu unneeded).
// grid (MTILES, KS) = 448 blocks, 256 threads = 8 warps.
// ---------------------------------------------------------------------------
__global__ void __launch_bounds__(256, 3) gemm_kernel(
        const float* __restrict__ x, const float* __restrict__ proto,
        float* __restrict__ out) {
    extern __shared__ char smem[];
    __nv_bfloat16* bbf = (__nv_bfloat16*)(smem + STAGES * STAGE_BYTES);

    const int mt   = blockIdx.x;
    const int ks   = blockIdx.y;
    const int t    = threadIdx.x;
    const int warp = t >> 5;
    const int lane = t & 31;
    const int q    = lane & 3;
    const int rr   = lane >> 2;       // 0..7
    const int b0   = mt * MT;
    const int k0   = ks * KCHUNK;

    // --- cp.async mappings (R8/R13) ---
    const int xrr = t >> 3;           // 0..31
    const int xch = t & 7;            // granule 0..7 (row = 8 granules = 128B)
    const float* xg0 = x + (size_t)(b0 + xrr) * K_DIM + k0 + xch * 4;
    const uint32_t a_sw = (uint32_t)(xch ^ ((xrr & 3) << 1));

    const int prr = t >> 2;           // 0..63 (only < NP participate)
    const int pch = t & 3;
    const float* pg0 = proto + (size_t)prr * K_DIM + k0 + pch * 4;
    const uint32_t b_sw0 = (uint32_t)( pch      ^ ((prr & 3) << 1));
    const uint32_t b_sw1 = (uint32_t)((pch + 4) ^ ((prr & 3) << 1));
    const int psz = (prr < P_DIM) ? 16 : 0;

    const uint32_t smem_u = (uint32_t)__cvta_generic_to_shared(smem);

    auto issue = [&](int stage, int chunk) {
        const uint32_t sb = smem_u + (uint32_t)(stage * STAGE_BYTES);
        const float* xg = xg0 + chunk * KB;
        #pragma unroll
        for (int pass = 0; pass < 4; pass++) {
            cpa16(sb + (uint32_t)((xrr + pass * 32) * 128) + (a_sw << 4),
                  xg + (size_t)(pass * 32) * K_DIM);
        }
        if (prr < NP) {
            const float* pg = pg0 + chunk * KB;
            const uint32_t bb = sb + AS_BYTES + (uint32_t)(prr * 128);
            cpa16z(bb + (b_sw0 << 4), pg,      psz);
            cpa16z(bb + (b_sw1 << 4), pg + 16, psz);
        }
        cpa_commit();
    };

    // prologue
    issue(0, 0);
    issue(1, 1);

    // fragment rows
    const int r0 = warp * 16 + rr;
    const int r1 = r0 + 8;
    const uint32_t swf = (uint32_t)((rr & 3) << 1);
    const int qg = q >> 1;
    const int qp = (q & 1) << 3;

    // convert-pass mapping (warps 0-6 = 224 threads; row = t>>2, quad pos t&3)
    const int crow = t >> 2;
    const int cp0  = (t & 3) * 2;                       // physical granule pair
    const uint32_t csw = (uint32_t)((crow & 3) << 1);

    float acc[7][4];
    #pragma unroll
    for (int j = 0; j < 7; j++)
        #pragma unroll
        for (int c = 0; c < 4; c++) acc[j][c] = 0.f;
    float x2a = 0.f, x2b = 0.f;
    float p2acc = 0.f;

    int stage = 0;
    for (int it = 0; it < NITER; ++it) {
        __syncthreads();                 // bf16 tile it-1 reads done; stage (it+2)%3 free
        const int nxt = it + 2;
        if (nxt < NITER) issue((stage + 2 >= STAGES) ? stage + 2 - STAGES : stage + 2, nxt);
        else             cpa_commit();   // keep group counting uniform
        cpa_wait2();                     // my copies for chunk `it` complete
        __syncthreads();                 // ALL threads' copies for chunk `it` visible

        const char* sb = smem + stage * STAGE_BYTES;

        // --- B convert: fp32 stage -> shared bf16 tile; exact p2 for free ---
        if (t < 224) {
            const char* bsrc = sb + AS_BYTES + crow * 128;
            float4 v0 = *(const float4*)(bsrc + (cp0 << 4));
            float4 v1 = *(const float4*)(bsrc + ((cp0 + 1) << 4));
            p2acc += v0.x * v0.x + v0.y * v0.y + v0.z * v0.z + v0.w * v0.w
                   + v1.x * v1.x + v1.y * v1.y + v1.z * v1.z + v1.w * v1.w;
            const uint32_t g0 = (uint32_t)cp0 ^ csw;    // even; logical granule
            uint4 w;
            w.x = pack_bf16x2(make_float2(v0.x, v0.y));
            w.y = pack_bf16x2(make_float2(v0.z, v0.w));
            w.z = pack_bf16x2(make_float2(v1.x, v1.y));
            w.w = pack_bf16x2(make_float2(v1.z, v1.w));
            *(uint4*)((char*)bbf + crow * 80 + (g0 << 3)) = w;
        }
        __syncthreads();                 // bf16 tile for chunk `it` ready

        if (++stage == STAGES) stage = 0;

        #pragma unroll
        for (int kk = 0; kk < 2; ++kk) {
            const uint32_t g0 = (uint32_t)(kk * 4 + qg);
            const uint32_t o_lo = ((g0 ^ swf) << 4) + qp;
            const uint32_t o_hi = (((g0 + 2) ^ swf) << 4) + qp;
            float2 a00 = *(const float2*)(sb + r0 * 128 + o_lo);
            float2 a01 = *(const float2*)(sb + r0 * 128 + o_hi);
            float2 a10 = *(const float2*)(sb + r1 * 128 + o_lo);
            float2 a11 = *(const float2*)(sb + r1 * 128 + o_hi);
            x2a += a00.x * a00.x + a00.y * a00.y + a01.x * a01.x + a01.y * a01.y;
            x2b += a10.x * a10.x + a10.y * a10.y + a11.x * a11.x + a11.y * a11.y;
            uint32_t A0 = pack_bf16x2(a00);
            uint32_t A1 = pack_bf16x2(a10);
            uint32_t A2 = pack_bf16x2(a01);
            uint32_t A3 = pack_bf16x2(a11);
            const int kb = kk * 16 + q * 2;
            #pragma unroll
            for (int j = 0; j < 7; j++) {
                const int n = j * 8 + rr;
                uint32_t B0 = *(const uint32_t*)&bbf[n * BPITCH + kb];
                uint32_t B1 = *(const uint32_t*)&bbf[n * BPITCH + kb + 8];
                asm volatile(
                    "mma.sync.aligned.m16n8k16.row.col.f32.bf16.bf16.f32 "
                    "{%0,%1,%2,%3}, {%4,%5,%6,%7}, {%8,%9}, {%0,%1,%2,%3};\n"
                    : "+f"(acc[j][0]), "+f"(acc[j][1]), "+f"(acc[j][2]), "+f"(acc[j][3])
                    : "r"(A0), "r"(A1), "r"(A2), "r"(A3), "r"(B0), "r"(B1));
            }
        }
    }

    // --- block epilogue ---

    // x^2 per row (quad reduce; all 4 lanes end with the row sum)
    x2a += __shfl_xor_sync(0xffffffffu, x2a, 1);
    x2a += __shfl_xor_sync(0xffffffffu, x2a, 2);
    x2b += __shfl_xor_sync(0xffffffffu, x2b, 1);
    x2b += __shfl_xor_sync(0xffffffffu, x2b, 2);

    // p^2 table from convert-thread partials (thread quad = one B row)
    __syncthreads();                      // done with pipeline smem
    float* p2s = (float*)smem;            // 56 floats
    if (t < 224) {
        float s = p2acc;
        s += __shfl_xor_sync(0xffffffffu, s, 1);
        s += __shfl_xor_sync(0xffffffffu, s, 2);
        if ((t & 3) == 0) p2s[t >> 2] = s;
    }
    __syncthreads();

    // v2 RED: out[b, n..n+1] += x2_row + p2_col - 2*xp  (relu unnecessary)
    float* out0 = out + (size_t)(b0 + r0) * P_DIM;
    float* out1 = out + (size_t)(b0 + r1) * P_DIM;
    const int ccol = q * 2;
    #pragma unroll
    for (int j = 0; j < 7; j++) {
        const int n0 = j * 8 + ccol;      // even; pair (n0, n0+1), 8B aligned
        if (n0 < P_DIM) {
            const float pv0 = p2s[n0];
            const float pv1 = p2s[n0 + 1];
            red_v2(out0 + n0, x2a + pv0 - 2.f * acc[j][0],
                              x2a + pv1 - 2.f * acc[j][1]);
            red_v2(out1 + n0, x2b + pv0 - 2.f * acc[j][2],
                              x2b + pv1 - 2.f * acc[j][3]);
        }
    }
}

// ---------------------------------------------------------------------------
extern "C" void kernel_launch(void* const* d_in, const int* in_sizes, int n_in,
                              void* d_out, int out_size) {
    const float* x     = (const float*)d_in[0];
    const float* proto = (const float*)d_in[1];
    if (in_sizes[0] == P_DIM * K_DIM) {  // defensive: swap if order differs
        x     = (const float*)d_in[1];
        proto = (const float*)d_in[0];
    }
    float* out = (float*)d_out;

    cudaFuncSetAttribute(gemm_kernel,
                         cudaFuncAttributeMaxDynamicSharedMemorySize, SMEM_BYTES);

    cudaMemsetAsync(out, 0, (size_t)B_DIM * P_DIM * sizeof(float));
    gemm_kernel<<<dim3(MTILES, KS), 256, SMEM_BYTES>>>(x, proto, out);
}

// round 16
// speedup vs baseline: 1.0316x; 1.0316x over previous
#include <cuda_runtime.h>
#include <cuda_bf16.h>
#include <cstdint>

// Problem constants
#define B_DIM   2048
#define P_DIM   50
#define K_DIM   28672            // 512*7*8
#define NP      56               // P padded to 56 (7 n8-tiles)
#define KS      28               // K splits (uniform NITER=32, grid 448)
#define KCHUNK  (K_DIM / KS)     // 1024
#define KB      32               // K floats per pipeline stage
#define NITER   (KCHUNK / KB)    // 32
#define MT      128              // M tile
#define MTILES  (B_DIM / MT)     // 16
#define STAGES  3
#define BPITCH  40               // bf16 pitch (80B rows; LDS.32 frag reads conflict-free)

// Staged tiles: fp32, exact 128B rows, XOR granule swizzle
#define AS_BYTES (MT * KB * 4)               // 16384
#define BS_BYTES (NP * KB * 4)               // 7168
#define STAGE_BYTES (AS_BYTES + BS_BYTES)    // 23552
#define BF_BYTES (NP * BPITCH * 2)           // 4480 single shared bf16 B tile
#define SMEM_BYTES (STAGES * STAGE_BYTES + BF_BYTES)   // 75136 (3 CTAs/SM: 220KB < 228KB)

// ---------------------------------------------------------------------------
__device__ __forceinline__ void cpa16(uint32_t saddr, const void* gaddr) {
    asm volatile("cp.async.cg.shared.global [%0], [%1], 16;\n"
                 :: "r"(saddr), "l"(gaddr));
}
// zero-fill variant: src-size=0 reads nothing, fills 16B of zeros
__device__ __forceinline__ void cpa16z(uint32_t saddr, const void* gaddr, int srcsz) {
    asm volatile("cp.async.cg.shared.global [%0], [%1], 16, %2;\n"
                 :: "r"(saddr), "l"(gaddr), "r"(srcsz));
}
__device__ __forceinline__ void cpa_commit() {
    asm volatile("cp.async.commit_group;\n" ::: "memory");
}
__device__ __forceinline__ void cpa_wait2() {
    asm volatile("cp.async.wait_group 2;\n" ::: "memory");
}
__device__ __forceinline__ uint32_t pack_bf16x2(float2 v) {
    __nv_bfloat162 h = __floats2bfloat162_rn(v.x, v.y);
    return *(uint32_t*)&h;
}
// vector reduction: out[0] += v0, out[1] += v1 in ONE LTS op (sm_90+)
__device__ __forceinline__ void red_v2(float* gaddr, float v0, float v1) {
    asm volatile("red.global.add.v2.f32 [%0], {%1, %2};\n"
                 :: "l"(gaddr), "f"(v0), "f"(v1) : "memory");
}

// ---------------------------------------------------------------------------
// Fused GEMM + distance accumulation, single kernel.
// Per iteration: cp.async fp32 A+B (3 stages) -> convert B fp32->bf16 into a
// single shared tile (warps 0-6; exact p2 accumulated from fp32 registers)
// -> MMA with fp32 A fragments (x^2 fused) and bf16 B fragments (LDS.32).
// Block epilogue: v2-RED  x2_b + p2_p - 2*xp  into out[b,p] (relu unneeded).
// grid (MTILES, KS) = 448 blocks, 256 threads = 8 warps.
// ---------------------------------------------------------------------------
__global__ void __launch_bounds__(256, 3) gemm_kernel(
        const float* __restrict__ x, const float* __restrict__ proto,
        float* __restrict__ out) {
    extern __shared__ char smem[];
    __nv_bfloat16* bbf = (__nv_bfloat16*)(smem + STAGES * STAGE_BYTES);

    const int mt   = blockIdx.x;
    const int ks   = blockIdx.y;
    const int t    = threadIdx.x;
    const int warp = t >> 5;
    const int lane = t & 31;
    const int q    = lane & 3;
    const int rr   = lane >> 2;       // 0..7
    const int b0   = mt * MT;
    const int k0   = ks * KCHUNK;

    // --- cp.async mappings (R8/R13) ---
    const int xrr = t >> 3;           // 0..31
    const int xch = t & 7;            // granule 0..7 (row = 8 granules = 128B)
    const float* xg0 = x + (size_t)(b0 + xrr) * K_DIM + k0 + xch * 4;
    const uint32_t a_sw = (uint32_t)(xch ^ ((xrr & 3) << 1));

    const int prr = t >> 2;           // 0..63 (only < NP participate)
    const int pch = t & 3;
    const float* pg0 = proto + (size_t)prr * K_DIM + k0 + pch * 4;
    const uint32_t b_sw0 = (uint32_t)( pch      ^ ((prr & 3) << 1));
    const uint32_t b_sw1 = (uint32_t)((pch + 4) ^ ((prr & 3) << 1));
    const int psz = (prr < P_DIM) ? 16 : 0;

    const uint32_t smem_u = (uint32_t)__cvta_generic_to_shared(smem);

    auto issue = [&](int stage, int chunk) {
        const uint32_t sb = smem_u + (uint32_t)(stage * STAGE_BYTES);
        const float* xg = xg0 + chunk * KB;
        #pragma unroll
        for (int pass = 0; pass < 4; pass++) {
            cpa16(sb + (uint32_t)((xrr + pass * 32) * 128) + (a_sw << 4),
                  xg + (size_t)(pass * 32) * K_DIM);
        }
        if (prr < NP) {
            const float* pg = pg0 + chunk * KB;
            const uint32_t bb = sb + AS_BYTES + (uint32_t)(prr * 128);
            cpa16z(bb + (b_sw0 << 4), pg,      psz);
            cpa16z(bb + (b_sw1 << 4), pg + 16, psz);
        }
        cpa_commit();
    };

    // prologue
    issue(0, 0);
    issue(1, 1);

    // fragment rows
    const int r0 = warp * 16 + rr;
    const int r1 = r0 + 8;
    const uint32_t swf = (uint32_t)((rr & 3) << 1);
    const int qg = q >> 1;
    const int qp = (q & 1) << 3;

    // convert-pass mapping (warps 0-6 = 224 threads; row = t>>2, quad pos t&3)
    const int crow = t >> 2;
    const int cp0  = (t & 3) * 2;                       // physical granule pair
    const uint32_t csw = (uint32_t)((crow & 3) << 1);

    float acc[7][4];
    #pragma unroll
    for (int j = 0; j < 7; j++)
        #pragma unroll
        for (int c = 0; c < 4; c++) acc[j][c] = 0.f;
    float x2a = 0.f, x2b = 0.f;
    float p2acc = 0.f;

    int stage = 0;
    for (int it = 0; it < NITER; ++it) {
        __syncthreads();                 // bf16 tile it-1 reads done; stage (it+2)%3 free
        const int nxt = it + 2;
        if (nxt < NITER) issue((stage + 2 >= STAGES) ? stage + 2 - STAGES : stage + 2, nxt);
        else             cpa_commit();   // keep group counting uniform
        cpa_wait2();                     // my copies for chunk `it` complete
        __syncthreads();                 // ALL threads' copies for chunk `it` visible

        const char* sb = smem + stage * STAGE_BYTES;

        // --- B convert: fp32 stage -> shared bf16 tile; exact p2 for free ---
        if (t < 224) {
            const char* bsrc = sb + AS_BYTES + crow * 128;
            float4 v0 = *(const float4*)(bsrc + (cp0 << 4));
            float4 v1 = *(const float4*)(bsrc + ((cp0 + 1) << 4));
            p2acc += v0.x * v0.x + v0.y * v0.y + v0.z * v0.z + v0.w * v0.w
                   + v1.x * v1.x + v1.y * v1.y + v1.z * v1.z + v1.w * v1.w;
            const uint32_t g0 = (uint32_t)cp0 ^ csw;    // even; logical granule
            uint4 w;
            w.x = pack_bf16x2(make_float2(v0.x, v0.y));
            w.y = pack_bf16x2(make_float2(v0.z, v0.w));
            w.z = pack_bf16x2(make_float2(v1.x, v1.y));
            w.w = pack_bf16x2(make_float2(v1.z, v1.w));
            *(uint4*)((char*)bbf + crow * 80 + (g0 << 3)) = w;
        }
        __syncthreads();                 // bf16 tile for chunk `it` ready

        if (++stage == STAGES) stage = 0;

        #pragma unroll
        for (int kk = 0; kk < 2; ++kk) {
            const uint32_t g0 = (uint32_t)(kk * 4 + qg);
            const uint32_t o_lo = ((g0 ^ swf) << 4) + qp;
            const uint32_t o_hi = (((g0 + 2) ^ swf) << 4) + qp;
            float2 a00 = *(const float2*)(sb + r0 * 128 + o_lo);
            float2 a01 = *(const float2*)(sb + r0 * 128 + o_hi);
            float2 a10 = *(const float2*)(sb + r1 * 128 + o_lo);
            float2 a11 = *(const float2*)(sb + r1 * 128 + o_hi);
            x2a += a00.x * a00.x + a00.y * a00.y + a01.x * a01.x + a01.y * a01.y;
            x2b += a10.x * a10.x + a10.y * a10.y + a11.x * a11.x + a11.y * a11.y;
            uint32_t A0 = pack_bf16x2(a00);
            uint32_t A1 = pack_bf16x2(a10);
            uint32_t A2 = pack_bf16x2(a01);
            uint32_t A3 = pack_bf16x2(a11);
            const int kb = kk * 16 + q * 2;
            #pragma unroll
            for (int j = 0; j < 7; j++) {
                const int n = j * 8 + rr;
                uint32_t B0 = *(const uint32_t*)&bbf[n * BPITCH + kb];
                uint32_t B1 = *(const uint32_t*)&bbf[n * BPITCH + kb + 8];
                asm volatile(
                    "mma.sync.aligned.m16n8k16.row.col.f32.bf16.bf16.f32 "
                    "{%0,%1,%2,%3}, {%4,%5,%6,%7}, {%8,%9}, {%0,%1,%2,%3};\n"
                    : "+f"(acc[j][0]), "+f"(acc[j][1]), "+f"(acc[j][2]), "+f"(acc[j][3])
                    : "r"(A0), "r"(A1), "r"(A2), "r"(A3), "r"(B0), "r"(B1));
            }
        }
    }

    // --- block epilogue ---

    // x^2 per row (quad reduce; all 4 lanes end with the row sum)
    x2a += __shfl_xor_sync(0xffffffffu, x2a, 1);
    x2a += __shfl_xor_sync(0xffffffffu, x2a, 2);
    x2b += __shfl_xor_sync(0xffffffffu, x2b, 1);
    x2b += __shfl_xor_sync(0xffffffffu, x2b, 2);

    // p^2 table from convert-thread partials (thread quad = one B row)
    __syncthreads();                      // done with pipeline smem
    float* p2s = (float*)smem;            // 56 floats
    if (t < 224) {
        float s = p2acc;
        s += __shfl_xor_sync(0xffffffffu, s, 1);
        s += __shfl_xor_sync(0xffffffffu, s, 2);
        if ((t & 3) == 0) p2s[t >> 2] = s;
    }
    __syncthreads();

    // v2 RED: out[b, n..n+1] += x2_row + p2_col - 2*xp  (relu unnecessary)
    float* out0 = out + (size_t)(b0 + r0) * P_DIM;
    float* out1 = out + (size_t)(b0 + r1) * P_DIM;
    const int ccol = q * 2;
    #pragma unroll
    for (int j = 0; j < 7; j++) {
        const int n0 = j * 8 + ccol;      // even; pair (n0, n0+1), 8B aligned
        if (n0 < P_DIM) {
            const float pv0 = p2s[n0];
            const float pv1 = p2s[n0 + 1];
            red_v2(out0 + n0, x2a + pv0 - 2.f * acc[j][0],
                              x2a + pv1 - 2.f * acc[j][1]);
            red_v2(out1 + n0, x2b + pv0 - 2.f * acc[j][2],
                              x2b + pv1 - 2.f * acc[j][3]);
        }
    }
}

// ---------------------------------------------------------------------------
extern "C" void kernel_launch(void* const* d_in, const int* in_sizes, int n_in,
                              void* d_out, int out_size) {
    const float* x     = (const float*)d_in[0];
    const float* proto = (const float*)d_in[1];
    if (in_sizes[0] == P_DIM * K_DIM) {  // defensive: swap if order differs
        x     = (const float*)d_in[1];
        proto = (const float*)d_in[0];
    }
    float* out = (float*)d_out;

    cudaFuncSetAttribute(gemm_kernel,
                         cudaFuncAttributeMaxDynamicSharedMemorySize, SMEM_BYTES);

    cudaMemsetAsync(out, 0, (size_t)B_DIM * P_DIM * sizeof(float));
    gemm_kernel<<<dim3(MTILES, KS), 256, SMEM_BYTES>>>(x, proto, out);
}